// round 13
// baseline (speedup 1.0000x reference)
#include <cuda_runtime.h>
#include <cuda_fp16.h>
#include <cstdint>

// Problem constants
#define B_    16
#define L_    4096
#define D_    512
#define D1_   256
#define DF_   64
#define H_    511            // (4096-16)/8 + 1
#define NROWS (B_*H_)        // 8176
#define M_    (B_*L_)        // 65536
#define NOCT  (M_/8)         // 8192 octet rows (512 per batch)
#define EPS_  1e-8f

// Scratch (no allocations allowed)
__device__ float g_S [(size_t)NOCT*D1_];     // octet sums of leaky(X@W1+b1)
__device__ float g_pp[NROWS*DF_];            // per-patch encodings
__device__ float g_z [NROWS*DF_];            // aggregated

// ---------------------------------------------------------------------------
// fp16 helpers
// ---------------------------------------------------------------------------
__device__ __forceinline__ uint32_t f2h2(float a, float b) {
    __half2 h = __floats2half2_rn(a, b);
    return *reinterpret_cast<uint32_t*>(&h);
}
__device__ __forceinline__ void mma_f16(float* d, const uint32_t* a, const uint32_t* b) {
    asm volatile(
        "mma.sync.aligned.m16n8k16.row.col.f32.f16.f16.f32 "
        "{%0,%1,%2,%3}, {%4,%5,%6,%7}, {%8,%9}, {%0,%1,%2,%3};"
        : "+f"(d[0]), "+f"(d[1]), "+f"(d[2]), "+f"(d[3])
        : "r"(a[0]), "r"(a[1]), "r"(a[2]), "r"(a[3]), "r"(b[0]), "r"(b[1]));
}
// fp16-accumulate variant (correction terms; merged to fp32 at epilogue)
__device__ __forceinline__ void mma_f16a(uint32_t* d, const uint32_t* a, const uint32_t* b) {
    asm volatile(
        "mma.sync.aligned.m16n8k16.row.col.f16.f16.f16.f16 "
        "{%0,%1}, {%2,%3,%4,%5}, {%6,%7}, {%0,%1};"
        : "+r"(d[0]), "+r"(d[1])
        : "r"(a[0]), "r"(a[1]), "r"(a[2]), "r"(a[3]), "r"(b[0]), "r"(b[1]));
}
__device__ __forceinline__ void ldsm_x4(uint32_t* r, uint32_t addr) {
    asm volatile("ldmatrix.sync.aligned.m8n8.x4.shared.b16 {%0,%1,%2,%3}, [%4];"
        : "=r"(r[0]), "=r"(r[1]), "=r"(r[2]), "=r"(r[3]) : "r"(addr));
}
__device__ __forceinline__ void ldsm_x4_t(uint32_t* r, uint32_t addr) {
    asm volatile("ldmatrix.sync.aligned.m8n8.x4.trans.shared.b16 {%0,%1,%2,%3}, [%4];"
        : "=r"(r[0]), "=r"(r[1]), "=r"(r[2]), "=r"(r[3]) : "r"(addr));
}

// ---------------------------------------------------------------------------
// Split-FP16 tensor-core GEMM1 with fused octet-sum epilogue:
//   S[oct, col] = sum_{8 rows of oct} leaky(X@W1 + b1)
// hh product: fp32 accumulate. hl+lh corrections: fp16 accumulate (values
// are ~1e-3 absolute; fp16 rounding adds ~3e-6 relative), merged once.
// ---------------------------------------------------------------------------
#define AST_B   80          // A row stride, bytes
#define BST_B   272         // B row stride, bytes
#define OFF_AL  10240       // 128*80
#define OFF_BH  20480
#define OFF_BL  29184       // +32*272
#define BUFSZ   37888       // per ping-pong buffer
#define GEMM_SMEM (2*BUFSZ) // 75776

__global__ void __launch_bounds__(256)
gemm_h(const float* __restrict__ A, const float* __restrict__ Bw,
       const float* __restrict__ bias, float* __restrict__ S,
       int M, int K, int N)
{
    extern __shared__ char smem[];
    const uint32_t sb = (uint32_t)__cvta_generic_to_shared(smem);

    const int tid  = threadIdx.x;
    const int warp = tid >> 5, lane = tid & 31;
    const int wm = warp >> 2, wn = warp & 3;

    float acc[4][4][4];
    uint32_t ch[4][4][2];
#pragma unroll
    for (int mt=0; mt<4; mt++)
#pragma unroll
        for (int nt=0; nt<4; nt++) {
#pragma unroll
            for (int c=0; c<4; c++) acc[mt][nt][c] = 0.f;
            ch[mt][nt][0] = 0u; ch[mt][nt][1] = 0u;
        }

    const float* Ab = A + (size_t)blockIdx.y*128*K;
    const float* Bb = Bw + blockIdx.x*128;

    int arow[4], acol[4];
#pragma unroll
    for (int i=0;i<4;i++) { int idx = tid + i*256; arow[i] = idx >> 3; acol[i] = (idx & 7)*4; }
    int bk[4], bn4[4];
#pragma unroll
    for (int i=0;i<4;i++) { int idx = tid + i*256; bk[i] = idx >> 5; bn4[i] = (idx & 31)*4; }

    const uint32_t aBase = sb + (uint32_t)((wm*64 + (lane & 15))*AST_B + ((lane >> 4)*16));
    const uint32_t bBase = sb + OFF_BH
        + (uint32_t)(((lane & 7) + ((lane >> 4) & 1)*8)*BST_B
                     + (wn*32 + ((lane >> 3) & 1)*8)*2);

    float4 ra[4], rb[4];

    auto gload = [&](int k0) {
#pragma unroll
        for (int i=0;i<4;i++)
            ra[i] = *(const float4*)&Ab[(size_t)arow[i]*K + k0 + acol[i]];
#pragma unroll
        for (int i=0;i<4;i++)
            rb[i] = *(const float4*)&Bb[(size_t)(k0 + bk[i])*N + bn4[i]];
    };
    auto sstore = [&](int bo) {
#pragma unroll
        for (int i=0;i<4;i++) {
            const float* v = (const float*)&ra[i];
            float h0 = __half2float(__float2half_rn(v[0]));
            float h1 = __half2float(__float2half_rn(v[1]));
            float h2 = __half2float(__float2half_rn(v[2]));
            float h3 = __half2float(__float2half_rn(v[3]));
            uint2 hh; hh.x = f2h2(h0, h1);       hh.y = f2h2(h2, h3);
            uint2 ll; ll.x = f2h2(v[0]-h0, v[1]-h1); ll.y = f2h2(v[2]-h2, v[3]-h3);
            const int byte = arow[i]*AST_B + acol[i]*2;
            *(uint2*)(smem + bo + byte)          = hh;
            *(uint2*)(smem + bo + OFF_AL + byte) = ll;
        }
#pragma unroll
        for (int i=0;i<4;i++) {
            const float* v = (const float*)&rb[i];
            float h0 = __half2float(__float2half_rn(v[0]));
            float h1 = __half2float(__float2half_rn(v[1]));
            float h2 = __half2float(__float2half_rn(v[2]));
            float h3 = __half2float(__float2half_rn(v[3]));
            uint2 hh; hh.x = f2h2(h0, h1);       hh.y = f2h2(h2, h3);
            uint2 ll; ll.x = f2h2(v[0]-h0, v[1]-h1); ll.y = f2h2(v[2]-h2, v[3]-h3);
            const int byte = bk[i]*BST_B + bn4[i]*2;
            *(uint2*)(smem + bo + OFF_BH + byte) = hh;
            *(uint2*)(smem + bo + OFF_BL + byte) = ll;
        }
    };

    gload(0);
    sstore(0);
    __syncthreads();

    int bo = 0;
    for (int k0 = 0; k0 < K; k0 += 32) {
        const bool has_next = (k0 + 32) < K;
        if (has_next) gload(k0 + 32);

#pragma unroll
        for (int s = 0; s < 2; s++) {
            uint32_t ah[4][4], al[4][4];
#pragma unroll
            for (int mt=0; mt<4; mt++) {
                const uint32_t aa = aBase + bo + mt*1280 + s*32;
                ldsm_x4(ah[mt], aa);
                ldsm_x4(al[mt], aa + OFF_AL);
            }
            uint32_t bh[4][2], bl[4][2];
            {
                uint32_t t[4];
                const uint32_t ba = bBase + bo + s*4352;
                ldsm_x4_t(t, ba);
                bh[0][0]=t[0]; bh[0][1]=t[2]; bh[1][0]=t[1]; bh[1][1]=t[3];
                ldsm_x4_t(t, ba + 32);
                bh[2][0]=t[0]; bh[2][1]=t[2]; bh[3][0]=t[1]; bh[3][1]=t[3];
                ldsm_x4_t(t, ba + (OFF_BL - OFF_BH));
                bl[0][0]=t[0]; bl[0][1]=t[2]; bl[1][0]=t[1]; bl[1][1]=t[3];
                ldsm_x4_t(t, ba + (OFF_BL - OFF_BH) + 32);
                bl[2][0]=t[0]; bl[2][1]=t[2]; bl[3][0]=t[1]; bl[3][1]=t[3];
            }
#pragma unroll
            for (int mt=0; mt<4; mt++)
#pragma unroll
                for (int nt=0; nt<4; nt++) {
                    mma_f16a(ch[mt][nt], al[mt], bh[nt]);   // lo*hi (f16 acc)
                    mma_f16a(ch[mt][nt], ah[mt], bl[nt]);   // hi*lo (f16 acc)
                    mma_f16(acc[mt][nt], ah[mt], bh[nt]);   // hi*hi (f32 acc)
                }
        }

        if (has_next) sstore(bo ^ BUFSZ);
        __syncthreads();
        bo ^= BUFSZ;
    }

    // Epilogue: merge f16 corrections, bias + leaky, octet sums via shuffles.
    const int t4 = lane & 3;
#pragma unroll
    for (int mt=0; mt<4; mt++) {
#pragma unroll
        for (int nt=0; nt<4; nt++) {
            const __half2 c0 = *(__half2*)&ch[mt][nt][0];
            const __half2 c1 = *(__half2*)&ch[mt][nt][1];
            const int c = blockIdx.x*128 + wn*32 + nt*8 + t4*2;
            const float b0 = bias[c], b1 = bias[c+1];
            float v00 = acc[mt][nt][0] + __low2float(c0)  + b0;
            float v01 = acc[mt][nt][1] + __high2float(c0) + b1;
            float v10 = acc[mt][nt][2] + __low2float(c1)  + b0;
            float v11 = acc[mt][nt][3] + __high2float(c1) + b1;
            v00 = (v00 > 0.f) ? v00 : 0.01f*v00;
            v01 = (v01 > 0.f) ? v01 : 0.01f*v01;
            v10 = (v10 > 0.f) ? v10 : 0.01f*v10;
            v11 = (v11 > 0.f) ? v11 : 0.01f*v11;
#pragma unroll
            for (int mask = 4; mask <= 16; mask <<= 1) {
                v00 += __shfl_xor_sync(0xffffffffu, v00, mask);
                v01 += __shfl_xor_sync(0xffffffffu, v01, mask);
                v10 += __shfl_xor_sync(0xffffffffu, v10, mask);
                v11 += __shfl_xor_sync(0xffffffffu, v11, mask);
            }
            if (lane < 4) {
                const size_t o0 = (size_t)blockIdx.y*16 + wm*8 + 2*mt;
                float2 s0; s0.x = v00; s0.y = v01;
                float2 s1; s1.x = v10; s1.y = v11;
                *(float2*)&S[o0*D1_ + c]     = s0;
                *(float2*)&S[(o0+1)*D1_ + c] = s1;
            }
        }
    }
}

// ---------------------------------------------------------------------------
// pp[n] = ((S[oct h] + S[oct h+1]) / 16) @ W2 + b2   (patch = two octets)
// ---------------------------------------------------------------------------
__global__ void __launch_bounds__(256)
pp_kernel(const float* __restrict__ S, const float* __restrict__ W2,
          const float* __restrict__ b2, float* __restrict__ pp)
{
    __shared__ float sP[8][D1_];
    const int tid = threadIdx.x;

#pragma unroll
    for (int rr = 0; rr < 8; rr++) {
        const int n = blockIdx.x*8 + rr;
        const int b = n / H_, h = n % H_;
        const float* s0 = S + ((size_t)b*512 + h)*D1_;
        sP[rr][tid] = (s0[tid] + s0[D1_ + tid]) * (1.f/16.f);
    }
    __syncthreads();

    const int i = tid & 63;
#pragma unroll
    for (int rr = tid >> 6; rr < 8; rr += 4) {
        float acc = b2[i];
#pragma unroll
        for (int j = 0; j < D1_; j++) acc += sP[rr][j] * W2[j*DF_ + i];
        pp[(blockIdx.x*8 + rr)*DF_ + i] = acc;
    }
}

// ---------------------------------------------------------------------------
// Fused per-row attention, 4 rows per 256-thread block.
// Two independent branchless 8-heaps (j<32 / j>=32) double the ILP of the
// serial compare-swap chain; exact merge via bitonic max(hA[t], hB[7-t])
// (keys unique: index embedded in low 6 bits, lowest-index tie-break).
// ---------------------------------------------------------------------------
__global__ void __launch_bounds__(256)
attn_kernel(const float* __restrict__ pp,
            const float* __restrict__ Wq, const float* __restrict__ Wk,
            const float* __restrict__ Wv,
            const float* __restrict__ Wagg, const float* __restrict__ bagg,
            float* __restrict__ z)
{
    const int r = threadIdx.x >> 6;
    const int i = threadIdx.x & 63;
    const int n = blockIdx.x*4 + r;

    __shared__ float sp[4][DF_], sq[4][DF_], sk[4][DF_], sv[4][DF_], sAv[4][DF_];

    sp[r][i] = pp[n*DF_ + i];
    __syncthreads();

    float q = 0.f, k = 0.f, v = 0.f;
#pragma unroll
    for (int j = 0; j < DF_; j++) {
        const float x = sp[r][j];
        q += x * Wq[j*DF_ + i];
        k += x * Wk[j*DF_ + i];
        v += x * Wv[j*DF_ + i];
    }
    sq[r][i] = q; sk[r][i] = k; sv[r][i] = v;
    __syncthreads();

    float nq = 0.f, nk = 0.f;
#pragma unroll
    for (int j = 0; j < DF_; j++) { nq += sq[r][j]*sq[r][j]; nk += sk[r][j]*sk[r][j]; }
    const float inv_nq = 1.f / (sqrtf(nq) + EPS_);
    const float inv_nk = 1.f / (sqrtf(nk) + EPS_);

    const float c1 = (sq[r][i]*inv_nq) * inv_nk;
    const float c2 = (sk[r][i]*inv_nk) * inv_nq;

    uint32_t hA[8], hB[8];
#pragma unroll
    for (int t = 0; t < 8; t++) { hA[t] = 0u; hB[t] = 0u; }

#pragma unroll
    for (int j = 0; j < 32; j++) {
        const float sa = c1*sk[r][j]    - c2*sq[r][j];
        const float sb = c1*sk[r][j+32] - c2*sq[r][j+32];
        uint32_t uA = __float_as_uint(sa);
        uA = ((int32_t)uA < 0) ? ~uA : (uA | 0x80000000u);
        uA = (uA & 0xFFFFFFC0u) | (uint32_t)(63 - j);
        uint32_t uB = __float_as_uint(sb);
        uB = ((int32_t)uB < 0) ? ~uB : (uB | 0x80000000u);
        uB = (uB & 0xFFFFFFC0u) | (uint32_t)(31 - j);   // 63-(j+32)
        hA[0] = (hA[0] > uA) ? hA[0] : uA;
        hB[0] = (hB[0] > uB) ? hB[0] : uB;
#pragma unroll
        for (int t = 0; t < 7; t++) {
            const uint32_t loA = (hA[t] < hA[t+1]) ? hA[t] : hA[t+1];
            const uint32_t hiA = (hA[t] < hA[t+1]) ? hA[t+1] : hA[t];
            hA[t] = loA; hA[t+1] = hiA;
            const uint32_t loB = (hB[t] < hB[t+1]) ? hB[t] : hB[t+1];
            const uint32_t hiB = (hB[t] < hB[t+1]) ? hB[t+1] : hB[t];
            hB[t] = loB; hB[t+1] = hiB;
        }
    }

    float sum8 = 0.f, av = 0.f;
#pragma unroll
    for (int t = 0; t < 8; t++) {
        const uint32_t u = (hA[t] > hB[7-t]) ? hA[t] : hB[7-t];  // bitonic top-8
        const int j = 63 - (int)(u & 63u);
        const float s = c1*sk[r][j] - c2*sq[r][j];
        if (s > 0.f) {
            const float e = __expf(2.f*s);
            const float a = 1.f - __fdividef(2.f, e + 1.f);
            sum8 += a;
            av   += a * sv[r][j];
        }
    }
    av *= 1.f / fmaxf(sum8, EPS_);

    sAv[r][i] = av;
    __syncthreads();

    float acc = bagg[i];
#pragma unroll
    for (int j = 0; j < DF_; j++) acc += sAv[r][j]*Wagg[j*DF_ + i];
    z[n*DF_ + i] = (acc > 0.f) ? acc : 0.01f*acc;
}

// ---------------------------------------------------------------------------
// Fused decode + overlap, smem-staged coalesced output.
// out[b, 8o+r, :] = za[b,o] @ Wdec + bdec  (identical for all r in 0..7),
// za[b,o] = (z[b,o-1]+z[b,o])/2 (edges single). Block = 8 octets; results
// staged in smem then streamed as contiguous 128KB of float4 stores.
// ---------------------------------------------------------------------------
#define ZOUT_SMEM (2048 + 64*132*4 + 8*512*4)   // za + ws + sOut = 52224

__global__ void __launch_bounds__(256)
zdec_out_kernel(const float* __restrict__ z, const float* __restrict__ Wdec,
                const float* __restrict__ bdec, float* __restrict__ out)
{
    extern __shared__ char smem[];
    float* za   = (float*)smem;                  // 8 x 64
    float* ws   = za + 512;                      // 64 x 132
    float* sOut = ws + 64*132;                   // 8 x 512

    const int tid = threadIdx.x;
    const int b   = blockIdx.x >> 6;             // 64 blocks per batch
    const int o0  = (blockIdx.x & 63) * 8;       // starting octet

    if (tid < 128) {
        const int row = tid >> 4;                // 0..7
        const int c4  = (tid & 15) * 4;
        const int o   = o0 + row;
        const int hA  = (o == 0)   ? 0   : o - 1;
        const int hB  = (o == 511) ? 510 : o;
        const float4 a  = *(const float4*)&z[((size_t)b*H_ + hA)*DF_ + c4];
        const float4 bb = *(const float4*)&z[((size_t)b*H_ + hB)*DF_ + c4];
        float4 o4;
        if (hA == hB) { o4 = a; }
        else {
            o4.x = (a.x + bb.x)*0.5f; o4.y = (a.y + bb.y)*0.5f;
            o4.z = (a.z + bb.z)*0.5f; o4.w = (a.w + bb.w)*0.5f;
        }
        *(float4*)&za[row*DF_ + c4] = o4;
    }

    const int ct64 = tid & 63;                   // column-pair index
    const int rt   = tid >> 6;                   // row group (2 rows each)

    for (int ct = 0; ct < 4; ct++) {             // 4 chunks of 128 cols
        __syncthreads();
#pragma unroll
        for (int i = 0; i < 8; i++) {
            const int idx = tid + i*256;
            const int rr = idx >> 5, c4 = (idx & 31)*4;
            *(float4*)&ws[rr*132 + c4] = *(const float4*)&Wdec[(size_t)rr*D_ + ct*128 + c4];
        }
        __syncthreads();

        const int c = ct*128 + ct64*2;
        const float bd0 = bdec[c], bd1 = bdec[c+1];

        float acc[2][2];
        acc[0][0]=0.f; acc[0][1]=0.f; acc[1][0]=0.f; acc[1][1]=0.f;
#pragma unroll
        for (int k = 0; k < DF_; k++) {
            const float2 w = *(const float2*)&ws[k*132 + ct64*2];
#pragma unroll
            for (int rr = 0; rr < 2; rr++) {
                const float zv = za[(rt*2+rr)*DF_ + k];
                acc[rr][0] += zv*w.x;
                acc[rr][1] += zv*w.y;
            }
        }
#pragma unroll
        for (int rr = 0; rr < 2; rr++) {
            float2 o2; o2.x = acc[rr][0] + bd0; o2.y = acc[rr][1] + bd1;
            *(float2*)&sOut[(rt*2+rr)*512 + c] = o2;
        }
    }
    __syncthreads();

    // Stream 64 contiguous output rows (8 octets x 8 reps) as float4.
    float* outBase = &out[((size_t)b*L_ + o0*8)*D_];
#pragma unroll
    for (int it = 0; it < 32; it++) {
        const int idx = tid + it*256;            // 0..8191 float4
        const float4 v = *(const float4*)&sOut[(idx >> 10)*512 + (idx & 127)*4];
        *(float4*)&outBase[(size_t)idx*4] = v;
    }
}

// ---------------------------------------------------------------------------
extern "C" void kernel_launch(void* const* d_in, const int* in_sizes, int n_in,
                              void* d_out, int out_size)
{
    const float* X    = (const float*)d_in[0];
    const float* W1   = (const float*)d_in[1];
    const float* b1   = (const float*)d_in[2];
    const float* W2   = (const float*)d_in[3];
    const float* b2   = (const float*)d_in[4];
    const float* Wq   = (const float*)d_in[5];
    const float* Wk   = (const float*)d_in[6];
    const float* Wv   = (const float*)d_in[7];
    const float* Wagg = (const float*)d_in[8];
    const float* bagg = (const float*)d_in[9];
    const float* Wdec = (const float*)d_in[10];
    const float* bdec = (const float*)d_in[11];
    float* out = (float*)d_out;

    float *S, *pp, *z;
    cudaGetSymbolAddress((void**)&S,  g_S);
    cudaGetSymbolAddress((void**)&pp, g_pp);
    cudaGetSymbolAddress((void**)&z,  g_z);

    cudaFuncSetAttribute(gemm_h,
        cudaFuncAttributeMaxDynamicSharedMemorySize, GEMM_SMEM);
    cudaFuncSetAttribute(zdec_out_kernel,
        cudaFuncAttributeMaxDynamicSharedMemorySize, ZOUT_SMEM);

    // 1) S = octet-sums of leaky(X @ W1 + b1)
    gemm_h<<<dim3(D1_/128, M_/128), 256, GEMM_SMEM>>>(X, W1, b1, S, M_, D_, D1_);

    // 2) pp = ((S[h] + S[h+1]) / 16) @ W2 + b2
    pp_kernel<<<NROWS/8, 256>>>(S, W2, b2, pp);

    // 3) fused qkv + attention + top-8 + aggregate
    attn_kernel<<<NROWS/4, 256>>>(pp, Wq, Wk, Wv, Wagg, bagg, z);

    // 4) out = broadcast( za @ Wdec + bdec )  (staged, coalesced)
    zdec_out_kernel<<<NOCT/8, 256, ZOUT_SMEM>>>(z, Wdec, bdec, out);
}

// round 15
// speedup vs baseline: 1.0659x; 1.0659x over previous
#include <cuda_runtime.h>
#include <cuda_fp16.h>
#include <cstdint>

// Problem constants
#define B_    16
#define L_    4096
#define D_    512
#define D1_   256
#define DF_   64
#define H_    511            // (4096-16)/8 + 1
#define NROWS (B_*H_)        // 8176
#define M_    (B_*L_)        // 65536
#define NOCT  (M_/8)         // 8192 octet rows (512 per batch)
#define EPS_  1e-8f

// Scratch (no allocations allowed)
__device__ float g_S [(size_t)NOCT*D1_];     // octet sums of leaky(X@W1+b1)
__device__ float g_pp[NROWS*DF_];            // per-patch encodings
__device__ float g_z [NROWS*DF_];            // aggregated

// ---------------------------------------------------------------------------
// fp16 helpers
// ---------------------------------------------------------------------------
__device__ __forceinline__ uint32_t f2h2(float a, float b) {
    __half2 h = __floats2half2_rn(a, b);
    return *reinterpret_cast<uint32_t*>(&h);
}
__device__ __forceinline__ void mma_f16(float* d, const uint32_t* a, const uint32_t* b) {
    asm volatile(
        "mma.sync.aligned.m16n8k16.row.col.f32.f16.f16.f32 "
        "{%0,%1,%2,%3}, {%4,%5,%6,%7}, {%8,%9}, {%0,%1,%2,%3};"
        : "+f"(d[0]), "+f"(d[1]), "+f"(d[2]), "+f"(d[3])
        : "r"(a[0]), "r"(a[1]), "r"(a[2]), "r"(a[3]), "r"(b[0]), "r"(b[1]));
}
// fp16-accumulate variant (correction terms; merged to fp32 at epilogue)
__device__ __forceinline__ void mma_f16a(uint32_t* d, const uint32_t* a, const uint32_t* b) {
    asm volatile(
        "mma.sync.aligned.m16n8k16.row.col.f16.f16.f16.f16 "
        "{%0,%1}, {%2,%3,%4,%5}, {%6,%7}, {%0,%1};"
        : "+r"(d[0]), "+r"(d[1])
        : "r"(a[0]), "r"(a[1]), "r"(a[2]), "r"(a[3]), "r"(b[0]), "r"(b[1]));
}
__device__ __forceinline__ void ldsm_x4(uint32_t* r, uint32_t addr) {
    asm volatile("ldmatrix.sync.aligned.m8n8.x4.shared.b16 {%0,%1,%2,%3}, [%4];"
        : "=r"(r[0]), "=r"(r[1]), "=r"(r[2]), "=r"(r[3]) : "r"(addr));
}
__device__ __forceinline__ void ldsm_x4_t(uint32_t* r, uint32_t addr) {
    asm volatile("ldmatrix.sync.aligned.m8n8.x4.trans.shared.b16 {%0,%1,%2,%3}, [%4];"
        : "=r"(r[0]), "=r"(r[1]), "=r"(r[2]), "=r"(r[3]) : "r"(addr));
}

// ---------------------------------------------------------------------------
// Split-FP16 tensor-core GEMM1 with fused octet-sum epilogue:
//   S[oct, col] = sum_{8 rows of oct} leaky(X@W1 + b1)
// BM=64 (warp tile 32x32) -> ~120 regs, 55.3KB smem, 2 CTAs/SM for latency
// hiding. hh: fp32 acc; hl+lh corrections: fp16 acc, merged at epilogue.
// ---------------------------------------------------------------------------
#define AST_B   80          // A row stride, bytes
#define BST_B   272         // B row stride, bytes
#define OFF_AL  5120        // 64*80
#define OFF_BH  10240
#define OFF_BL  18944       // +32*272
#define BUFSZ   27648       // per ping-pong buffer
#define GEMM_SMEM (2*BUFSZ) // 55296

__global__ void __launch_bounds__(256, 2)
gemm_h(const float* __restrict__ A, const float* __restrict__ Bw,
       const float* __restrict__ bias, float* __restrict__ S,
       int M, int K, int N)
{
    extern __shared__ char smem[];
    const uint32_t sb = (uint32_t)__cvta_generic_to_shared(smem);

    const int tid  = threadIdx.x;
    const int warp = tid >> 5, lane = tid & 31;
    const int wm = warp >> 2, wn = warp & 3;

    float acc[2][4][4];
    uint32_t ch[2][4][2];
#pragma unroll
    for (int mt=0; mt<2; mt++)
#pragma unroll
        for (int nt=0; nt<4; nt++) {
#pragma unroll
            for (int c=0; c<4; c++) acc[mt][nt][c] = 0.f;
            ch[mt][nt][0] = 0u; ch[mt][nt][1] = 0u;
        }

    const float* Ab = A + (size_t)blockIdx.y*64*K;
    const float* Bb = Bw + blockIdx.x*128;

    int arow[2], acol[2];
#pragma unroll
    for (int i=0;i<2;i++) { int idx = tid + i*256; arow[i] = idx >> 3; acol[i] = (idx & 7)*4; }
    int bk[4], bn4[4];
#pragma unroll
    for (int i=0;i<4;i++) { int idx = tid + i*256; bk[i] = idx >> 5; bn4[i] = (idx & 31)*4; }

    const uint32_t aBase = sb + (uint32_t)((wm*32 + (lane & 15))*AST_B + ((lane >> 4)*16));
    const uint32_t bBase = sb + OFF_BH
        + (uint32_t)(((lane & 7) + ((lane >> 4) & 1)*8)*BST_B
                     + (wn*32 + ((lane >> 3) & 1)*8)*2);

    float4 ra[2], rb[4];

    auto gload = [&](int k0) {
#pragma unroll
        for (int i=0;i<2;i++)
            ra[i] = *(const float4*)&Ab[(size_t)arow[i]*K + k0 + acol[i]];
#pragma unroll
        for (int i=0;i<4;i++)
            rb[i] = *(const float4*)&Bb[(size_t)(k0 + bk[i])*N + bn4[i]];
    };
    auto sstore = [&](int bo) {
#pragma unroll
        for (int i=0;i<2;i++) {
            const float* v = (const float*)&ra[i];
            float h0 = __half2float(__float2half_rn(v[0]));
            float h1 = __half2float(__float2half_rn(v[1]));
            float h2 = __half2float(__float2half_rn(v[2]));
            float h3 = __half2float(__float2half_rn(v[3]));
            uint2 hh; hh.x = f2h2(h0, h1);       hh.y = f2h2(h2, h3);
            uint2 ll; ll.x = f2h2(v[0]-h0, v[1]-h1); ll.y = f2h2(v[2]-h2, v[3]-h3);
            const int byte = arow[i]*AST_B + acol[i]*2;
            *(uint2*)(smem + bo + byte)          = hh;
            *(uint2*)(smem + bo + OFF_AL + byte) = ll;
        }
#pragma unroll
        for (int i=0;i<4;i++) {
            const float* v = (const float*)&rb[i];
            float h0 = __half2float(__float2half_rn(v[0]));
            float h1 = __half2float(__float2half_rn(v[1]));
            float h2 = __half2float(__float2half_rn(v[2]));
            float h3 = __half2float(__float2half_rn(v[3]));
            uint2 hh; hh.x = f2h2(h0, h1);       hh.y = f2h2(h2, h3);
            uint2 ll; ll.x = f2h2(v[0]-h0, v[1]-h1); ll.y = f2h2(v[2]-h2, v[3]-h3);
            const int byte = bk[i]*BST_B + bn4[i]*2;
            *(uint2*)(smem + bo + OFF_BH + byte) = hh;
            *(uint2*)(smem + bo + OFF_BL + byte) = ll;
        }
    };

    gload(0);
    sstore(0);
    __syncthreads();

    int bo = 0;
    for (int k0 = 0; k0 < K; k0 += 32) {
        const bool has_next = (k0 + 32) < K;
        if (has_next) gload(k0 + 32);

#pragma unroll
        for (int s = 0; s < 2; s++) {
            uint32_t ah[2][4], al[2][4];
#pragma unroll
            for (int mt=0; mt<2; mt++) {
                const uint32_t aa = aBase + bo + mt*1280 + s*32;
                ldsm_x4(ah[mt], aa);
                ldsm_x4(al[mt], aa + OFF_AL);
            }
            uint32_t bh[4][2], bl[4][2];
            {
                uint32_t t[4];
                const uint32_t ba = bBase + bo + s*4352;
                ldsm_x4_t(t, ba);
                bh[0][0]=t[0]; bh[0][1]=t[2]; bh[1][0]=t[1]; bh[1][1]=t[3];
                ldsm_x4_t(t, ba + 32);
                bh[2][0]=t[0]; bh[2][1]=t[2]; bh[3][0]=t[1]; bh[3][1]=t[3];
                ldsm_x4_t(t, ba + (OFF_BL - OFF_BH));
                bl[0][0]=t[0]; bl[0][1]=t[2]; bl[1][0]=t[1]; bl[1][1]=t[3];
                ldsm_x4_t(t, ba + (OFF_BL - OFF_BH) + 32);
                bl[2][0]=t[0]; bl[2][1]=t[2]; bl[3][0]=t[1]; bl[3][1]=t[3];
            }
#pragma unroll
            for (int mt=0; mt<2; mt++)
#pragma unroll
                for (int nt=0; nt<4; nt++) {
                    mma_f16a(ch[mt][nt], al[mt], bh[nt]);   // lo*hi (f16 acc)
                    mma_f16a(ch[mt][nt], ah[mt], bl[nt]);   // hi*lo (f16 acc)
                    mma_f16(acc[mt][nt], ah[mt], bh[nt]);   // hi*hi (f32 acc)
                }
        }

        if (has_next) sstore(bo ^ BUFSZ);
        __syncthreads();
        bo ^= BUFSZ;
    }

    // Epilogue: merge f16 corrections, bias + leaky, octet sums via shuffles.
    const int t4 = lane & 3;
#pragma unroll
    for (int mt=0; mt<2; mt++) {
#pragma unroll
        for (int nt=0; nt<4; nt++) {
            const __half2 c0 = *(__half2*)&ch[mt][nt][0];
            const __half2 c1 = *(__half2*)&ch[mt][nt][1];
            const int c = blockIdx.x*128 + wn*32 + nt*8 + t4*2;
            const float b0 = bias[c], b1 = bias[c+1];
            float v00 = acc[mt][nt][0] + __low2float(c0)  + b0;
            float v01 = acc[mt][nt][1] + __high2float(c0) + b1;
            float v10 = acc[mt][nt][2] + __low2float(c1)  + b0;
            float v11 = acc[mt][nt][3] + __high2float(c1) + b1;
            v00 = (v00 > 0.f) ? v00 : 0.01f*v00;
            v01 = (v01 > 0.f) ? v01 : 0.01f*v01;
            v10 = (v10 > 0.f) ? v10 : 0.01f*v10;
            v11 = (v11 > 0.f) ? v11 : 0.01f*v11;
#pragma unroll
            for (int mask = 4; mask <= 16; mask <<= 1) {
                v00 += __shfl_xor_sync(0xffffffffu, v00, mask);
                v01 += __shfl_xor_sync(0xffffffffu, v01, mask);
                v10 += __shfl_xor_sync(0xffffffffu, v10, mask);
                v11 += __shfl_xor_sync(0xffffffffu, v11, mask);
            }
            if (lane < 4) {
                const size_t o0 = (size_t)blockIdx.y*8 + wm*4 + 2*mt;
                float2 s0; s0.x = v00; s0.y = v01;
                float2 s1; s1.x = v10; s1.y = v11;
                *(float2*)&S[o0*D1_ + c]     = s0;
                *(float2*)&S[(o0+1)*D1_ + c] = s1;
            }
        }
    }
}

// ---------------------------------------------------------------------------
// pp[n] = ((S[oct h] + S[oct h+1]) / 16) @ W2 + b2   (patch = two octets)
// ---------------------------------------------------------------------------
__global__ void __launch_bounds__(256)
pp_kernel(const float* __restrict__ S, const float* __restrict__ W2,
          const float* __restrict__ b2, float* __restrict__ pp)
{
    __shared__ float sP[8][D1_];
    const int tid = threadIdx.x;

#pragma unroll
    for (int rr = 0; rr < 8; rr++) {
        const int n = blockIdx.x*8 + rr;
        const int b = n / H_, h = n % H_;
        const float* s0 = S + ((size_t)b*512 + h)*D1_;
        sP[rr][tid] = (s0[tid] + s0[D1_ + tid]) * (1.f/16.f);
    }
    __syncthreads();

    const int i = tid & 63;
#pragma unroll
    for (int rr = tid >> 6; rr < 8; rr += 4) {
        float acc = b2[i];
#pragma unroll
        for (int j = 0; j < D1_; j++) acc += sP[rr][j] * W2[j*DF_ + i];
        pp[(blockIdx.x*8 + rr)*DF_ + i] = acc;
    }
}

// ---------------------------------------------------------------------------
// Fused per-row attention, 4 rows per 256-thread block (two-heap top-8).
// ---------------------------------------------------------------------------
__global__ void __launch_bounds__(256)
attn_kernel(const float* __restrict__ pp,
            const float* __restrict__ Wq, const float* __restrict__ Wk,
            const float* __restrict__ Wv,
            const float* __restrict__ Wagg, const float* __restrict__ bagg,
            float* __restrict__ z)
{
    const int r = threadIdx.x >> 6;
    const int i = threadIdx.x & 63;
    const int n = blockIdx.x*4 + r;

    __shared__ float sp[4][DF_], sq[4][DF_], sk[4][DF_], sv[4][DF_], sAv[4][DF_];

    sp[r][i] = pp[n*DF_ + i];
    __syncthreads();

    float q = 0.f, k = 0.f, v = 0.f;
#pragma unroll
    for (int j = 0; j < DF_; j++) {
        const float x = sp[r][j];
        q += x * Wq[j*DF_ + i];
        k += x * Wk[j*DF_ + i];
        v += x * Wv[j*DF_ + i];
    }
    sq[r][i] = q; sk[r][i] = k; sv[r][i] = v;
    __syncthreads();

    float nq = 0.f, nk = 0.f;
#pragma unroll
    for (int j = 0; j < DF_; j++) { nq += sq[r][j]*sq[r][j]; nk += sk[r][j]*sk[r][j]; }
    const float inv_nq = 1.f / (sqrtf(nq) + EPS_);
    const float inv_nk = 1.f / (sqrtf(nk) + EPS_);

    const float c1 = (sq[r][i]*inv_nq) * inv_nk;
    const float c2 = (sk[r][i]*inv_nk) * inv_nq;

    uint32_t hA[8], hB[8];
#pragma unroll
    for (int t = 0; t < 8; t++) { hA[t] = 0u; hB[t] = 0u; }

#pragma unroll
    for (int j = 0; j < 32; j++) {
        const float sa = c1*sk[r][j]    - c2*sq[r][j];
        const float sb = c1*sk[r][j+32] - c2*sq[r][j+32];
        uint32_t uA = __float_as_uint(sa);
        uA = ((int32_t)uA < 0) ? ~uA : (uA | 0x80000000u);
        uA = (uA & 0xFFFFFFC0u) | (uint32_t)(63 - j);
        uint32_t uB = __float_as_uint(sb);
        uB = ((int32_t)uB < 0) ? ~uB : (uB | 0x80000000u);
        uB = (uB & 0xFFFFFFC0u) | (uint32_t)(31 - j);   // 63-(j+32)
        hA[0] = (hA[0] > uA) ? hA[0] : uA;
        hB[0] = (hB[0] > uB) ? hB[0] : uB;
#pragma unroll
        for (int t = 0; t < 7; t++) {
            const uint32_t loA = (hA[t] < hA[t+1]) ? hA[t] : hA[t+1];
            const uint32_t hiA = (hA[t] < hA[t+1]) ? hA[t+1] : hA[t];
            hA[t] = loA; hA[t+1] = hiA;
            const uint32_t loB = (hB[t] < hB[t+1]) ? hB[t] : hB[t+1];
            const uint32_t hiB = (hB[t] < hB[t+1]) ? hB[t+1] : hB[t];
            hB[t] = loB; hB[t+1] = hiB;
        }
    }

    float sum8 = 0.f, av = 0.f;
#pragma unroll
    for (int t = 0; t < 8; t++) {
        const uint32_t u = (hA[t] > hB[7-t]) ? hA[t] : hB[7-t];  // bitonic top-8
        const int j = 63 - (int)(u & 63u);
        const float s = c1*sk[r][j] - c2*sq[r][j];
        if (s > 0.f) {
            const float e = __expf(2.f*s);
            const float a = 1.f - __fdividef(2.f, e + 1.f);
            sum8 += a;
            av   += a * sv[r][j];
        }
    }
    av *= 1.f / fmaxf(sum8, EPS_);

    sAv[r][i] = av;
    __syncthreads();

    float acc = bagg[i];
#pragma unroll
    for (int j = 0; j < DF_; j++) acc += sAv[r][j]*Wagg[j*DF_ + i];
    z[n*DF_ + i] = (acc > 0.f) ? acc : 0.01f*acc;
}

// ---------------------------------------------------------------------------
// Fused decode + overlap, direct float4 broadcast stores.
// out[b, 8o+r, :] = za[b,o] @ Wdec + bdec  (identical for r in 0..7),
// za[b,o] = (z[b,o-1]+z[b,o])/2 (edges single). Block = 16 octets, grid 512.
// Thread handles a column QUAD -> all broadcast stores are STG.128.
// ---------------------------------------------------------------------------
__global__ void __launch_bounds__(256)
zdec_out_kernel(const float* __restrict__ z, const float* __restrict__ Wdec,
                const float* __restrict__ bdec, float* __restrict__ out)
{
    __shared__ float za[16*DF_];
    __shared__ float ws[DF_*132];
    const int tid = threadIdx.x;
    const int b   = blockIdx.x >> 5;          // 32 blocks per batch
    const int o0  = (blockIdx.x & 31) * 16;   // starting octet in batch

    {
        const int row = tid >> 4;             // 0..15
        const int c4  = (tid & 15) * 4;
        const int o   = o0 + row;
        const int hA  = (o == 0)   ? 0   : o - 1;
        const int hB  = (o == 511) ? 510 : o;
        const float4 a  = *(const float4*)&z[((size_t)b*H_ + hA)*DF_ + c4];
        const float4 bb = *(const float4*)&z[((size_t)b*H_ + hB)*DF_ + c4];
        float4 o4;
        if (hA == hB) { o4 = a; }
        else {
            o4.x = (a.x + bb.x)*0.5f; o4.y = (a.y + bb.y)*0.5f;
            o4.z = (a.z + bb.z)*0.5f; o4.w = (a.w + bb.w)*0.5f;
        }
        *(float4*)&za[row*DF_ + c4] = o4;
    }

    const int cq = tid & 31;                  // column quad (4 cols)
    const int rt = tid >> 5;                  // row group (2 rows each)

    for (int ct = 0; ct < 4; ct++) {          // 4 chunks of 128 cols
        __syncthreads();
#pragma unroll
        for (int i = 0; i < 8; i++) {
            const int idx = tid + i*256;
            const int rr = idx >> 5, c4 = (idx & 31)*4;
            *(float4*)&ws[rr*132 + c4] = *(const float4*)&Wdec[(size_t)rr*D_ + ct*128 + c4];
        }
        __syncthreads();

        const float4 bd = *(const float4*)&bdec[ct*128 + cq*4];

        float acc[2][4];
#pragma unroll
        for (int rr=0;rr<2;rr++)
#pragma unroll
            for (int c=0;c<4;c++) acc[rr][c] = 0.f;
#pragma unroll
        for (int k = 0; k < DF_; k++) {
            const float4 w = *(const float4*)&ws[k*132 + cq*4];
#pragma unroll
            for (int rr = 0; rr < 2; rr++) {
                const float zv = za[(rt*2+rr)*DF_ + k];
                acc[rr][0] += zv*w.x; acc[rr][1] += zv*w.y;
                acc[rr][2] += zv*w.z; acc[rr][3] += zv*w.w;
            }
        }
#pragma unroll
        for (int rr = 0; rr < 2; rr++) {
            float4 v;
            v.x = acc[rr][0] + bd.x; v.y = acc[rr][1] + bd.y;
            v.z = acc[rr][2] + bd.z; v.w = acc[rr][3] + bd.w;
            const int o = o0 + rt*2 + rr;
            float* orow = &out[((size_t)b*L_ + 8*o)*D_ + ct*128 + cq*4];
#pragma unroll
            for (int rep = 0; rep < 8; rep++)
                *(float4*)&orow[(size_t)rep*D_] = v;
        }
    }
}

// ---------------------------------------------------------------------------
extern "C" void kernel_launch(void* const* d_in, const int* in_sizes, int n_in,
                              void* d_out, int out_size)
{
    const float* X    = (const float*)d_in[0];
    const float* W1   = (const float*)d_in[1];
    const float* b1   = (const float*)d_in[2];
    const float* W2   = (const float*)d_in[3];
    const float* b2   = (const float*)d_in[4];
    const float* Wq   = (const float*)d_in[5];
    const float* Wk   = (const float*)d_in[6];
    const float* Wv   = (const float*)d_in[7];
    const float* Wagg = (const float*)d_in[8];
    const float* bagg = (const float*)d_in[9];
    const float* Wdec = (const float*)d_in[10];
    const float* bdec = (const float*)d_in[11];
    float* out = (float*)d_out;

    float *S, *pp, *z;
    cudaGetSymbolAddress((void**)&S,  g_S);
    cudaGetSymbolAddress((void**)&pp, g_pp);
    cudaGetSymbolAddress((void**)&z,  g_z);

    cudaFuncSetAttribute(gemm_h,
        cudaFuncAttributeMaxDynamicSharedMemorySize, GEMM_SMEM);

    // 1) S = octet-sums of leaky(X @ W1 + b1)   (BM=64, 2 CTAs/SM)
    gemm_h<<<dim3(D1_/128, M_/64), 256, GEMM_SMEM>>>(X, W1, b1, S, M_, D_, D1_);

    // 2) pp = ((S[h] + S[h+1]) / 16) @ W2 + b2
    pp_kernel<<<NROWS/8, 256>>>(S, W2, b2, pp);

    // 3) fused qkv + attention + top-8 + aggregate
    attn_kernel<<<NROWS/4, 256>>>(pp, Wq, Wk, Wv, Wagg, bagg, z);

    // 4) out = broadcast( za @ Wdec + bdec )   (direct STG.128)
    zdec_out_kernel<<<NOCT/16, 256>>>(z, Wdec, bdec, out);
}